// round 2
// baseline (speedup 1.0000x reference)
#include <cuda_runtime.h>
#include <cuda_bf16.h>

#define NV   100000
#define ND   128
#define NE   600000
#define NVD  (NV * ND)

// ---------------- scratch (device globals: no allocation allowed) ------------
__device__ float g_f[NVD];      // activations between layers
__device__ float g_h0[NVD];     // W0 branch
__device__ float g_y[NVD];      // W1 branch (gathered over edges)
__device__ float g_h[NVD];      // pre-BN result
__device__ int   g_deg[NV];
__device__ int   g_rowptr[NV + 1];
__device__ int   g_cursor[NV];
__device__ int   g_adj[2 * NE];
__device__ float g_stats[2 * ND];   // [0..127] sum, [128..255] sumsq
__device__ float g_mr[2 * ND];      // [0..127] mean, [128..255] rstd
__device__ int   g_is64;            // edge dtype flag (1 = int64, 0 = int32)

// ---------------- edge dtype probe ------------------------------------------
// jnp.int64 silently becomes int32 when jax x64 is disabled. Probe the raw
// bytes: interpreting int32-pair data as int64 yields values >= 2^32 almost
// surely, while true int64 indices are all in [0, NV).
__global__ void k_detect(const void* __restrict__ edges) {
    const long long* e = (const long long*)edges;
    int ok = 1;
    for (int i = 0; i < 16; i++) {
        long long v = e[i];
        if (v < 0 || v >= NV) ok = 0;
    }
    g_is64 = ok;
}

// ---------------- CSR build --------------------------------------------------
__global__ void k_zero_deg() {
    int i = blockIdx.x * blockDim.x + threadIdx.x;
    if (i < NV) g_deg[i] = 0;
}

__device__ __forceinline__ void load_edge(const void* edges, int e, int& a, int& b) {
    if (g_is64) {
        longlong2 p = ((const longlong2*)edges)[e];
        a = (int)p.x; b = (int)p.y;
    } else {
        int2 p = ((const int2*)edges)[e];
        a = p.x; b = p.y;
    }
}

__global__ void k_count(const void* __restrict__ edges) {
    int e = blockIdx.x * blockDim.x + threadIdx.x;
    if (e < NE) {
        int a, b;
        load_edge(edges, e, a, b);
        atomicAdd(&g_deg[a], 1);
        atomicAdd(&g_deg[b], 1);
    }
}

// single-block exclusive scan of g_deg -> g_rowptr, g_cursor
__global__ void k_scan() {
    __shared__ int warpsums[32];
    __shared__ int s_carry;
    int tid = threadIdx.x;       // 1024 threads
    int lane = tid & 31, wid = tid >> 5;
    if (tid == 0) s_carry = 0;
    __syncthreads();
    for (int base = 0; base < NV; base += 1024) {
        int idx = base + tid;
        int val = (idx < NV) ? g_deg[idx] : 0;
        int inc = val;
        #pragma unroll
        for (int off = 1; off < 32; off <<= 1) {
            int t = __shfl_up_sync(0xFFFFFFFFu, inc, off);
            if (lane >= off) inc += t;
        }
        if (lane == 31) warpsums[wid] = inc;
        __syncthreads();
        if (wid == 0) {
            int ws = warpsums[lane];
            #pragma unroll
            for (int off = 1; off < 32; off <<= 1) {
                int t = __shfl_up_sync(0xFFFFFFFFu, ws, off);
                if (lane >= off) ws += t;
            }
            warpsums[lane] = ws;   // inclusive over warp totals
        }
        __syncthreads();
        int warpoff = (wid > 0) ? warpsums[wid - 1] : 0;
        int excl = s_carry + warpoff + inc - val;
        if (idx < NV) { g_rowptr[idx] = excl; g_cursor[idx] = excl; }
        int blocktotal = warpsums[31];
        __syncthreads();
        if (tid == 0) s_carry += blocktotal;
        __syncthreads();
    }
    if (tid == 0) g_rowptr[NV] = s_carry;   // == 2E
}

__global__ void k_fill(const void* __restrict__ edges) {
    int e = blockIdx.x * blockDim.x + threadIdx.x;
    if (e < NE) {
        int a, b;
        load_edge(edges, e, a, b);
        int pa = atomicAdd(&g_cursor[a], 1);
        g_adj[pa] = b;
        int pb = atomicAdd(&g_cursor[b], 1);
        g_adj[pb] = a;
    }
}

// ---------------- GEMM: C[i,j] = sum_k A[i,k]*W[j,k] + bias[j] ---------------
#define BM 128
#define BN 128
#define BK 16
#define TM 8
#define TN 8

__global__ __launch_bounds__(256, 2)
void k_gemm(const float* __restrict__ A, const float* __restrict__ W,
            const float* __restrict__ bias, float* __restrict__ C) {
    __shared__ float As[BK][BM];
    __shared__ float Bs[BK][BN];
    int tid = threadIdx.x;                 // 256
    int rowBase = blockIdx.x * BM;
    int tr = tid >> 4, tc = tid & 15;      // 16x16 thread tiles of 8x8

    float acc[TM][TN];
    #pragma unroll
    for (int m = 0; m < TM; m++)
        #pragma unroll
        for (int n = 0; n < TN; n++) acc[m][n] = 0.f;

    for (int k0 = 0; k0 < ND; k0 += BK) {
        #pragma unroll
        for (int i = 0; i < 2; i++) {
            int s  = i * 256 + tid;        // 512 float4 slots
            int r  = s >> 2;
            int kq = (s & 3) << 2;
            float4 av = make_float4(0.f, 0.f, 0.f, 0.f);
            if (rowBase + r < NV)
                av = *(const float4*)(A + (size_t)(rowBase + r) * ND + k0 + kq);
            As[kq + 0][r] = av.x; As[kq + 1][r] = av.y;
            As[kq + 2][r] = av.z; As[kq + 3][r] = av.w;
            float4 bv = *(const float4*)(W + (size_t)r * ND + k0 + kq);
            Bs[kq + 0][r] = bv.x; Bs[kq + 1][r] = bv.y;
            Bs[kq + 2][r] = bv.z; Bs[kq + 3][r] = bv.w;
        }
        __syncthreads();
        #pragma unroll
        for (int k = 0; k < BK; k++) {
            float a[TM], b[TN];
            #pragma unroll
            for (int m = 0; m < TM; m++) a[m] = As[k][tr * TM + m];
            #pragma unroll
            for (int n = 0; n < TN; n++) b[n] = Bs[k][tc * TN + n];
            #pragma unroll
            for (int m = 0; m < TM; m++)
                #pragma unroll
                for (int n = 0; n < TN; n++) acc[m][n] += a[m] * b[n];
        }
        __syncthreads();
    }

    float bb[TN];
    #pragma unroll
    for (int n = 0; n < TN; n++) bb[n] = __ldg(bias + tc * TN + n);
    #pragma unroll
    for (int m = 0; m < TM; m++) {
        int row = rowBase + tr * TM + m;
        if (row < NV) {
            float* cp = C + (size_t)row * ND + tc * TN;
            float4 o0 = make_float4(acc[m][0] + bb[0], acc[m][1] + bb[1],
                                    acc[m][2] + bb[2], acc[m][3] + bb[3]);
            float4 o1 = make_float4(acc[m][4] + bb[4], acc[m][5] + bb[5],
                                    acc[m][6] + bb[6], acc[m][7] + bb[7]);
            ((float4*)cp)[0] = o0;
            ((float4*)cp)[1] = o1;
        }
    }
}

// ---------------- misc -------------------------------------------------------
__global__ void k_zero_stats() {
    int i = threadIdx.x;
    if (i < 2 * ND) g_stats[i] = 0.f;
}

__global__ void k_finalize() {
    int c = threadIdx.x;   // 128
    float mean = g_stats[c] * (1.0f / NV);
    float var  = g_stats[ND + c] * (1.0f / NV) - mean * mean;
    g_mr[c]      = mean;
    g_mr[ND + c] = rsqrtf(var + 1e-5f);
}

// ---------------- aggregate: out[v] = h0[v] + sum_{u in N(v)} y[u] -----------
// one warp per node, lane covers 4 consecutive columns (float4).
__global__ void k_agg(const float* __restrict__ h0, const float* __restrict__ y,
                      float* __restrict__ out, int doStats) {
    int lane   = threadIdx.x & 31;
    int warp   = (blockIdx.x * blockDim.x + threadIdx.x) >> 5;
    int nwarps = (gridDim.x * blockDim.x) >> 5;

    float4 csum = make_float4(0.f, 0.f, 0.f, 0.f);
    float4 csq  = make_float4(0.f, 0.f, 0.f, 0.f);

    for (int v = warp; v < NV; v += nwarps) {
        float4 acc = ((const float4*)(h0 + (size_t)v * ND))[lane];
        int beg = g_rowptr[v], end = g_rowptr[v + 1];
        int j = beg;
        for (; j + 1 < end; j += 2) {
            int u0 = g_adj[j], u1 = g_adj[j + 1];
            float4 a0 = ((const float4*)(y + (size_t)u0 * ND))[lane];
            float4 a1 = ((const float4*)(y + (size_t)u1 * ND))[lane];
            acc.x += a0.x + a1.x; acc.y += a0.y + a1.y;
            acc.z += a0.z + a1.z; acc.w += a0.w + a1.w;
        }
        if (j < end) {
            int u0 = g_adj[j];
            float4 a0 = ((const float4*)(y + (size_t)u0 * ND))[lane];
            acc.x += a0.x; acc.y += a0.y; acc.z += a0.z; acc.w += a0.w;
        }
        ((float4*)(out + (size_t)v * ND))[lane] = acc;
        if (doStats) {
            csum.x += acc.x; csum.y += acc.y; csum.z += acc.z; csum.w += acc.w;
            csq.x += acc.x * acc.x; csq.y += acc.y * acc.y;
            csq.z += acc.z * acc.z; csq.w += acc.w * acc.w;
        }
    }
    if (doStats) {
        int c = lane * 4;
        atomicAdd(&g_stats[c + 0], csum.x);
        atomicAdd(&g_stats[c + 1], csum.y);
        atomicAdd(&g_stats[c + 2], csum.z);
        atomicAdd(&g_stats[c + 3], csum.w);
        atomicAdd(&g_stats[ND + c + 0], csq.x);
        atomicAdd(&g_stats[ND + c + 1], csq.y);
        atomicAdd(&g_stats[ND + c + 2], csq.z);
        atomicAdd(&g_stats[ND + c + 3], csq.w);
    }
}

// ---------------- BN normalize + optional residual + ReLU --------------------
__global__ void k_norm(const float* __restrict__ h, float* __restrict__ f,
                       const float* __restrict__ gamma, const float* __restrict__ beta,
                       const float* __restrict__ res) {
    int i = blockIdx.x * blockDim.x + threadIdx.x;   // float4 index
    if (i >= NVD / 4) return;
    int col4 = i & (ND / 4 - 1);                      // 0..31
    float4 hv = ((const float4*)h)[i];
    float4 mu = ((const float4*)g_mr)[col4];
    float4 rs = ((const float4*)(g_mr + ND))[col4];
    float4 ga = __ldg((const float4*)gamma + col4);
    float4 be = __ldg((const float4*)beta + col4);
    float4 o;
    o.x = (hv.x - mu.x) * rs.x * ga.x + be.x;
    o.y = (hv.y - mu.y) * rs.y * ga.y + be.y;
    o.z = (hv.z - mu.z) * rs.z * ga.z + be.z;
    o.w = (hv.w - mu.w) * rs.w * ga.w + be.w;
    if (res) {
        float4 rv = ((const float4*)res)[i];
        o.x += rv.x; o.y += rv.y; o.z += rv.z; o.w += rv.w;
    }
    o.x = fmaxf(o.x, 0.f); o.y = fmaxf(o.y, 0.f);
    o.z = fmaxf(o.z, 0.f); o.w = fmaxf(o.w, 0.f);
    ((float4*)f)[i] = o;
}

// ---------------- launch -----------------------------------------------------
extern "C" void kernel_launch(void* const* d_in, const int* in_sizes, int n_in,
                              void* d_out, int out_size) {
    const float* feat  = (const float*)d_in[0];
    const void*  edges = d_in[1];
    const float* W0    = (const float*)d_in[2];
    const float* b0    = (const float*)d_in[3];
    const float* W1    = (const float*)d_in[4];
    const float* b1    = (const float*)d_in[5];
    const float* gamma = (const float*)d_in[6];
    const float* beta  = (const float*)d_in[7];
    float*       out   = (float*)d_out;

    float* pf;  cudaGetSymbolAddress((void**)&pf,  g_f);
    float* ph0; cudaGetSymbolAddress((void**)&ph0, g_h0);
    float* py;  cudaGetSymbolAddress((void**)&py,  g_y);
    float* ph;  cudaGetSymbolAddress((void**)&ph,  g_h);

    // CSR build (once per call; reused by all 4 layers)
    k_detect<<<1, 1>>>(edges);
    k_zero_deg<<<(NV + 255) / 256, 256>>>();
    k_count<<<(NE + 255) / 256, 256>>>(edges);
    k_scan<<<1, 1024>>>();
    k_fill<<<(NE + 255) / 256, 256>>>(edges);

    const int gemmBlocks = (NV + BM - 1) / BM;   // 782
    const float* x = feat;
    for (int L = 0; L < 4; L++) {
        k_gemm<<<gemmBlocks, 256>>>(x, W0 + L * ND * ND, b0 + L * ND, ph0);
        k_gemm<<<gemmBlocks, 256>>>(x, W1 + L * ND * ND, b1 + L * ND, py);
        if (L < 3) {
            k_zero_stats<<<1, 256>>>();
            k_agg<<<2048, 256>>>(ph0, py, ph, 1);
            k_finalize<<<1, ND>>>();
            const float* res = (L == 2) ? feat : nullptr;
            k_norm<<<(NVD / 4 + 255) / 256, 256>>>(ph, pf, gamma + L * ND,
                                                   beta + L * ND, res);
            x = pf;
        } else {
            k_agg<<<2048, 256>>>(ph0, py, out, 0);
        }
    }
}